// round 7
// baseline (speedup 1.0000x reference)
#include <cuda_runtime.h>
#include <cuda_bf16.h>
#include <cstdint>

#define MAXN 50000
#define HCH  128

typedef __nv_bfloat16 bf16;

// ---------------- scratch (static device globals) ----------------
__device__ float g_hL[(size_t)MAXN * HCH];
__device__ float g_hG[(size_t)MAXN * HCH];
__device__ float g_aL[(size_t)MAXN * HCH];
__device__ float g_aG[(size_t)MAXN * HCH];
__device__ float g_xA[(size_t)MAXN * HCH];
__device__ float g_xB[(size_t)MAXN * HCH];
__device__ float g_iL[MAXN];
__device__ float g_iG[MAXN];
__device__ int   g_dL[MAXN];
__device__ int   g_dG[MAXN];
__device__ bf16  g_xhi[(size_t)MAXN * HCH];
__device__ bf16  g_xlo[(size_t)MAXN * HCH];
__device__ bf16  g_aLhi[(size_t)MAXN * HCH];
__device__ bf16  g_aLlo[(size_t)MAXN * HCH];
__device__ bf16  g_aGhi[(size_t)MAXN * HCH];
__device__ bf16  g_aGlo[(size_t)MAXN * HCH];
__device__ bf16  g_whi[12 * 16384];
__device__ bf16  g_wlo[12 * 16384];

// ---------------- helpers ----------------
__device__ __forceinline__ uint32_t smem_u32(const void* p) {
    uint32_t a;
    asm("{ .reg .u64 t; cvta.to.shared.u64 t, %1; cvt.u32.u64 %0, t; }" : "=r"(a) : "l"(p));
    return a;
}
__device__ __forceinline__ void ldsm4(uint32_t addr, uint32_t& r0, uint32_t& r1,
                                      uint32_t& r2, uint32_t& r3) {
    asm volatile("ldmatrix.sync.aligned.m8n8.x4.shared.b16 {%0,%1,%2,%3}, [%4];"
                 : "=r"(r0), "=r"(r1), "=r"(r2), "=r"(r3) : "r"(addr));
}
__device__ __forceinline__ void mma16816(float (&d)[4], uint32_t a0, uint32_t a1,
                                         uint32_t a2, uint32_t a3, uint32_t b0, uint32_t b1) {
    asm volatile(
        "mma.sync.aligned.m16n8k16.row.col.f32.bf16.bf16.f32 "
        "{%0,%1,%2,%3}, {%4,%5,%6,%7}, {%8,%9}, {%0,%1,%2,%3};"
        : "+f"(d[0]), "+f"(d[1]), "+f"(d[2]), "+f"(d[3])
        : "r"(a0), "r"(a1), "r"(a2), "r"(a3), "r"(b0), "r"(b1));
}

// smem tile: 128 rows x 136 bf16 (136 = 128 + 8 pad -> conflict-free ldmatrix)
static constexpr int TROW  = 136;                 // elements per row
static constexpr int TELEM = 128 * TROW;          // 17408 elements per tile
static constexpr int TBYTES = TELEM * 2;          // 34816 bytes
static constexpr int SM_DUAL = 6 * TBYTES;        // 208896
static constexpr int SM_CAT  = 4 * TBYTES;        // 139264

// stage [128 x 128] bf16 row-major tile into smem [128][136]
__device__ __forceinline__ void stage(const bf16* __restrict__ g, bf16* s,
                                      int nvalid, int t) {
    for (int i = t; i < 2048; i += 256) {
        int row = i >> 4, c = i & 15;
        uint4 v = make_uint4(0u, 0u, 0u, 0u);
        if (row < nvalid) v = *(const uint4*)(g + (size_t)row * 128 + c * 8);
        *(uint4*)(s + row * TROW + c * 8) = v;
    }
}

__device__ __forceinline__ void bsplit2(float x, float y, bf16* hi, bf16* lo) {
    bf16 h0 = __float2bfloat16(x), h1 = __float2bfloat16(y);
    *(__nv_bfloat162*)hi = __halves2bfloat162(h0, h1);
    *(__nv_bfloat162*)lo = __halves2bfloat162(
        __float2bfloat16(x - __bfloat162float(h0)),
        __float2bfloat16(y - __bfloat162float(h1)));
}

// ---------------- degree / dinv ----------------
__global__ void k_degzero(int* dL, int* dG, int n) {
    int i = blockIdx.x * blockDim.x + threadIdx.x;
    if (i < n) { dL[i] = 0; dG[i] = 0; }
}
__global__ void k_count(const int* __restrict__ dst, int E, int* __restrict__ deg) {
    int e = blockIdx.x * blockDim.x + threadIdx.x;
    if (e < E) atomicAdd(&deg[dst[e]], 1);
}
__global__ void k_dinv(const int* __restrict__ dL, const int* __restrict__ dG,
                       float* __restrict__ iL, float* __restrict__ iG, int n) {
    int i = blockIdx.x * blockDim.x + threadIdx.x;
    if (i < n) {
        iL[i] = rsqrtf((float)dL[i] + 2.0f);
        iG[i] = rsqrtf((float)dG[i] + 2.0f);
    }
}

// ---------------- weight convert: transpose + bf16 hi/lo split ----------------
// for layer l: mats (l*4+0)=WL^T, (+1)=WG^T, (+2)=linW[0:128]^T, (+3)=linW[128:256]^T
// mat layout: [n][k] (k contiguous) -> exactly what ldmatrix-based B wants
__global__ __launch_bounds__(256) void k_cvtW(
    const float* __restrict__ WL, const float* __restrict__ WG, const float* __restrict__ linW,
    bf16* __restrict__ hi, bf16* __restrict__ lo)
{
    int idx = blockIdx.x * 256 + threadIdx.x;
    if (idx >= 12 * 16384) return;
    int matid = idx >> 14, e = idx & 16383;
    int nn = e >> 7, k = e & 127;
    int l = matid >> 2, which = matid & 3;
    float v;
    if (which == 0)      v = WL[(size_t)l * 16384 + k * 128 + nn];
    else if (which == 1) v = WG[(size_t)l * 16384 + k * 128 + nn];
    else if (which == 2) v = linW[(size_t)l * 32768 + k * 128 + nn];
    else                 v = linW[(size_t)l * 32768 + (k + 128) * 128 + nn];
    bf16 h = __float2bfloat16(v);
    hi[idx] = h;
    lo[idx] = __float2bfloat16(v - __bfloat162float(h));
}

__global__ __launch_bounds__(256) void k_cvtX(
    const float* __restrict__ x, bf16* __restrict__ hi, bf16* __restrict__ lo, int total)
{
    int i = blockIdx.x * 256 + threadIdx.x;
    if (i >= total) return;
    float v = x[i];
    bf16 h = __float2bfloat16(v);
    hi[i] = h;
    lo[i] = __float2bfloat16(v - __bfloat162float(h));
}

// ---------------- dual GCN GEMM (HMMA):  h = (A@W)*dinv,  aInit = 2*h ----------------
__global__ __launch_bounds__(256) void gemm_gcn_dual(
    const bf16* __restrict__ Ahi, const bf16* __restrict__ Alo,
    const bf16* __restrict__ BLhi, const bf16* __restrict__ BLlo,
    const bf16* __restrict__ BGhi, const bf16* __restrict__ BGlo,
    const float* __restrict__ iL, const float* __restrict__ iG,
    float* __restrict__ hL, float* __restrict__ hG,
    float* __restrict__ aL, float* __restrict__ aG, int M)
{
    extern __shared__ bf16 sm[];
    bf16* sA[2]  = { sm,             sm + TELEM };      // hi, lo
    bf16* sBL[2] = { sm + 2 * TELEM, sm + 3 * TELEM };
    bf16* sBG[2] = { sm + 4 * TELEM, sm + 5 * TELEM };
    int t = threadIdx.x;
    int row0 = blockIdx.x * 128;
    int nv = M - row0; if (nv > 128) nv = 128;

    stage(Ahi + (size_t)row0 * 128, sA[0], nv, t);
    stage(Alo + (size_t)row0 * 128, sA[1], nv, t);
    stage(BLhi, sBL[0], 128, t);
    stage(BLlo, sBL[1], 128, t);
    stage(BGhi, sBG[0], 128, t);
    stage(BGlo, sBG[1], 128, t);
    __syncthreads();

    int wid = t >> 5, lid = t & 31;
    int wr = wid & 3, wc = wid >> 2;

    float acc[2][2][8][4];   // [L/G][mb][nb][frag]
#pragma unroll
    for (int o = 0; o < 2; o++)
#pragma unroll
        for (int mb = 0; mb < 2; mb++)
#pragma unroll
            for (int nb = 0; nb < 8; nb++)
#pragma unroll
                for (int j = 0; j < 4; j++) acc[o][mb][nb][j] = 0.0f;

    // ldmatrix lane address components (bytes)
    uint32_t a_lane = (uint32_t)(wr * 32 + (lid & 15)) * (TROW * 2) + ((lid & 16) ? 16u : 0u);
    uint32_t b_lane = (uint32_t)((lid & 7) + ((lid & 16) ? 8 : 0) + wc * 64) * (TROW * 2)
                    + ((lid & 8) ? 16u : 0u);

    uint32_t aBase[2]  = { smem_u32(sA[0]),  smem_u32(sA[1]) };
    uint32_t blBase[2] = { smem_u32(sBL[0]), smem_u32(sBL[1]) };
    uint32_t bgBase[2] = { smem_u32(sBG[0]), smem_u32(sBG[1]) };

#pragma unroll
    for (int pass = 0; pass < 3; pass++) {
        uint32_t ab  = aBase[pass == 2 ? 1 : 0] + a_lane;
        uint32_t blb = blBase[pass == 1 ? 1 : 0] + b_lane;
        uint32_t bgb = bgBase[pass == 1 ? 1 : 0] + b_lane;
#pragma unroll
        for (int kk = 0; kk < 8; kk++) {
            uint32_t af[2][4];
            ldsm4(ab + kk * 32,                    af[0][0], af[0][1], af[0][2], af[0][3]);
            ldsm4(ab + kk * 32 + 16 * (TROW * 2),  af[1][0], af[1][1], af[1][2], af[1][3]);
#pragma unroll
            for (int nbp = 0; nbp < 4; nbp++) {
                uint32_t boff = (uint32_t)(nbp * 16) * (TROW * 2) + kk * 32;
                uint32_t b0, b1, b2, b3;
                ldsm4(blb + boff, b0, b1, b2, b3);
                mma16816(acc[0][0][2 * nbp],     af[0][0], af[0][1], af[0][2], af[0][3], b0, b1);
                mma16816(acc[0][0][2 * nbp + 1], af[0][0], af[0][1], af[0][2], af[0][3], b2, b3);
                mma16816(acc[0][1][2 * nbp],     af[1][0], af[1][1], af[1][2], af[1][3], b0, b1);
                mma16816(acc[0][1][2 * nbp + 1], af[1][0], af[1][1], af[1][2], af[1][3], b2, b3);
                ldsm4(bgb + boff, b0, b1, b2, b3);
                mma16816(acc[1][0][2 * nbp],     af[0][0], af[0][1], af[0][2], af[0][3], b0, b1);
                mma16816(acc[1][0][2 * nbp + 1], af[0][0], af[0][1], af[0][2], af[0][3], b2, b3);
                mma16816(acc[1][1][2 * nbp],     af[1][0], af[1][1], af[1][2], af[1][3], b0, b1);
                mma16816(acc[1][1][2 * nbp + 1], af[1][0], af[1][1], af[1][2], af[1][3], b2, b3);
            }
        }
    }

    // epilogue: h = acc * dinv[row]; aInit = 2*h
    int rb = row0 + wr * 32 + (lid >> 2);
    int cb = wc * 64 + (lid & 3) * 2;
#pragma unroll
    for (int o = 0; o < 2; o++) {
        const float* dv = o ? iG : iL;
        float* hd = o ? hG : hL;
        float* ad = o ? aG : aL;
#pragma unroll
        for (int mb = 0; mb < 2; mb++) {
            int r0 = rb + mb * 16, r1 = r0 + 8;
            float s0 = (r0 < M) ? dv[r0] : 0.0f;
            float s1 = (r1 < M) ? dv[r1] : 0.0f;
#pragma unroll
            for (int nb = 0; nb < 8; nb++) {
                float* a = acc[o][mb][nb];
                int col = cb + nb * 8;
                if (r0 < M) {
                    float2 h = make_float2(a[0] * s0, a[1] * s0);
                    *(float2*)(hd + (size_t)r0 * 128 + col) = h;
                    *(float2*)(ad + (size_t)r0 * 128 + col) = make_float2(2.0f * h.x, 2.0f * h.y);
                }
                if (r1 < M) {
                    float2 h = make_float2(a[2] * s1, a[3] * s1);
                    *(float2*)(hd + (size_t)r1 * 128 + col) = h;
                    *(float2*)(ad + (size_t)r1 * 128 + col) = make_float2(2.0f * h.x, 2.0f * h.y);
                }
            }
        }
    }
}

// ---------------- concat GEMM (HMMA): xout = A0@B0 + A1@B1 + linb; + bf16 hi/lo split ----------------
__global__ __launch_bounds__(256) void gemm_cat(
    const bf16* __restrict__ A0hi, const bf16* __restrict__ A0lo,
    const bf16* __restrict__ A1hi, const bf16* __restrict__ A1lo,
    const bf16* __restrict__ B0hi, const bf16* __restrict__ B0lo,
    const bf16* __restrict__ B1hi, const bf16* __restrict__ B1lo,
    const float* __restrict__ linb,
    float* __restrict__ xout, bf16* __restrict__ xhi, bf16* __restrict__ xlo, int M)
{
    extern __shared__ bf16 sm[];
    bf16* sA[2] = { sm,             sm + TELEM };
    bf16* sB[2] = { sm + 2 * TELEM, sm + 3 * TELEM };
    int t = threadIdx.x;
    int row0 = blockIdx.x * 128;
    int nv = M - row0; if (nv > 128) nv = 128;

    int wid = t >> 5, lid = t & 31;
    int wr = wid & 3, wc = wid >> 2;

    float acc[2][8][4];
#pragma unroll
    for (int mb = 0; mb < 2; mb++)
#pragma unroll
        for (int nb = 0; nb < 8; nb++)
#pragma unroll
            for (int j = 0; j < 4; j++) acc[mb][nb][j] = 0.0f;

    uint32_t a_lane = (uint32_t)(wr * 32 + (lid & 15)) * (TROW * 2) + ((lid & 16) ? 16u : 0u);
    uint32_t b_lane = (uint32_t)((lid & 7) + ((lid & 16) ? 8 : 0) + wc * 64) * (TROW * 2)
                    + ((lid & 8) ? 16u : 0u);
    uint32_t aBase[2] = { smem_u32(sA[0]), smem_u32(sA[1]) };
    uint32_t bBase[2] = { smem_u32(sB[0]), smem_u32(sB[1]) };

    const bf16* Ah[2] = { A0hi, A1hi };
    const bf16* Al[2] = { A0lo, A1lo };
    const bf16* Bh[2] = { B0hi, B1hi };
    const bf16* Bl[2] = { B0lo, B1lo };

    for (int ph = 0; ph < 2; ph++) {
        if (ph) __syncthreads();   // previous phase's reads done before restage
        stage(Ah[ph] + (size_t)row0 * 128, sA[0], nv, t);
        stage(Al[ph] + (size_t)row0 * 128, sA[1], nv, t);
        stage(Bh[ph], sB[0], 128, t);
        stage(Bl[ph], sB[1], 128, t);
        __syncthreads();
#pragma unroll
        for (int pass = 0; pass < 3; pass++) {
            uint32_t ab = aBase[pass == 2 ? 1 : 0] + a_lane;
            uint32_t bb = bBase[pass == 1 ? 1 : 0] + b_lane;
#pragma unroll
            for (int kk = 0; kk < 8; kk++) {
                uint32_t af[2][4];
                ldsm4(ab + kk * 32,                   af[0][0], af[0][1], af[0][2], af[0][3]);
                ldsm4(ab + kk * 32 + 16 * (TROW * 2), af[1][0], af[1][1], af[1][2], af[1][3]);
#pragma unroll
                for (int nbp = 0; nbp < 4; nbp++) {
                    uint32_t b0, b1, b2, b3;
                    ldsm4(bb + (uint32_t)(nbp * 16) * (TROW * 2) + kk * 32, b0, b1, b2, b3);
                    mma16816(acc[0][2 * nbp],     af[0][0], af[0][1], af[0][2], af[0][3], b0, b1);
                    mma16816(acc[0][2 * nbp + 1], af[0][0], af[0][1], af[0][2], af[0][3], b2, b3);
                    mma16816(acc[1][2 * nbp],     af[1][0], af[1][1], af[1][2], af[1][3], b0, b1);
                    mma16816(acc[1][2 * nbp + 1], af[1][0], af[1][1], af[1][2], af[1][3], b2, b3);
                }
            }
        }
    }

    int rb = row0 + wr * 32 + (lid >> 2);
    int cb = wc * 64 + (lid & 3) * 2;
#pragma unroll
    for (int mb = 0; mb < 2; mb++) {
        int r0 = rb + mb * 16, r1 = r0 + 8;
#pragma unroll
        for (int nb = 0; nb < 8; nb++) {
            float* a = acc[mb][nb];
            int col = cb + nb * 8;
            float2 lb = *(const float2*)(linb + col);
            if (r0 < M) {
                size_t off = (size_t)r0 * 128 + col;
                float vx = a[0] + lb.x, vy = a[1] + lb.y;
                *(float2*)(xout + off) = make_float2(vx, vy);
                bsplit2(vx, vy, xhi + off, xlo + off);
            }
            if (r1 < M) {
                size_t off = (size_t)r1 * 128 + col;
                float vx = a[2] + lb.x, vy = a[3] + lb.y;
                *(float2*)(xout + off) = make_float2(vx, vy);
                bsplit2(vx, vy, xhi + off, xlo + off);
            }
        }
    }
}

// ---------------- edge scatter-add: agg[dst] += hs[src] ----------------
__global__ __launch_bounds__(256) void k_edge(
    const float* __restrict__ hs,
    const int* __restrict__ src, const int* __restrict__ dst,
    float* __restrict__ agg, int E)
{
    int w = (int)((blockIdx.x * 256u + threadIdx.x) >> 5);
    if (w >= E) return;
    int lane = threadIdx.x & 31;
    int s = __ldg(src + w);
    int d = __ldg(dst + w);
    float4 v = *(const float4*)(hs + (size_t)s * 128 + lane * 4);
    float* p = agg + (size_t)d * 128 + lane * 4;
    asm volatile("red.global.add.v4.f32 [%0], {%1, %2, %3, %4};"
                 :: "l"(p), "f"(v.x), "f"(v.y), "f"(v.z), "f"(v.w)
                 : "memory");
}

// ---------------- LN(u*dinv + bias) -> relu -> (+res), write bf16 hi/lo ----------------
__global__ __launch_bounds__(256) void k_ln(
    const float* __restrict__ u, const float* __restrict__ dinv, const float* __restrict__ bias,
    const float* __restrict__ g, const float* __restrict__ b,
    const float* __restrict__ res,
    bf16* __restrict__ ohi, bf16* __restrict__ olo, int n)
{
    int w = (int)((blockIdx.x * 256u + threadIdx.x) >> 5);
    if (w >= n) return;
    int lane = threadIdx.x & 31;
    size_t off = (size_t)w * 128 + lane * 4;
    float di = __ldg(dinv + w);
    float4 v = *(const float4*)(u + off);
    float4 bb = *(const float4*)(bias + lane * 4);
    v.x = v.x * di + bb.x; v.y = v.y * di + bb.y;
    v.z = v.z * di + bb.z; v.w = v.w * di + bb.w;
    float s = v.x + v.y + v.z + v.w;
#pragma unroll
    for (int o = 16; o; o >>= 1) s += __shfl_xor_sync(0xffffffffu, s, o);
    float mu = s * (1.0f / 128.0f);
    float4 xc = make_float4(v.x - mu, v.y - mu, v.z - mu, v.w - mu);
    float q = xc.x * xc.x + xc.y * xc.y + xc.z * xc.z + xc.w * xc.w;
#pragma unroll
    for (int o = 16; o; o >>= 1) q += __shfl_xor_sync(0xffffffffu, q, o);
    float r = rsqrtf(q * (1.0f / 128.0f) + 1e-5f);
    float4 g4 = *(const float4*)(g + lane * 4);
    float4 b4 = *(const float4*)(b + lane * 4);
    float4 o4;
    o4.x = fmaxf(xc.x * r * g4.x + b4.x, 0.0f);
    o4.y = fmaxf(xc.y * r * g4.y + b4.y, 0.0f);
    o4.z = fmaxf(xc.z * r * g4.z + b4.z, 0.0f);
    o4.w = fmaxf(xc.w * r * g4.w + b4.w, 0.0f);
    if (res) {
        float4 rv = *(const float4*)(res + off);
        o4.x += rv.x; o4.y += rv.y; o4.z += rv.z; o4.w += rv.w;
    }
    bsplit2(o4.x, o4.y, ohi + off,     olo + off);
    bsplit2(o4.z, o4.w, ohi + off + 2, olo + off + 2);
}

// ---------------- final: proj = x @ finW + finb (N x 64), plus passthrough copy of x ----------------
__global__ __launch_bounds__(256) void k_final(
    const float* __restrict__ x, const float* __restrict__ W,
    const float* __restrict__ bias, float* proj, float* xdst,
    int n, int do_proj, int do_copy)
{
    __shared__ float Ws[128 * 64];
    __shared__ float xs[16 * 128];
    int t = threadIdx.x;
    if (do_proj) {
        for (int i = t; i < 128 * 64; i += 256) Ws[i] = W[i];
    }
    int row0 = blockIdx.x * 16;
    for (int i = t; i < 16 * 32; i += 256) {
        int r  = i >> 5;
        int c4 = (i & 31) * 4;
        int row = row0 + r;
        float4 v = (row < n) ? *(const float4*)(x + (size_t)row * 128 + c4)
                             : make_float4(0.f, 0.f, 0.f, 0.f);
        *(float4*)&xs[r * 128 + c4] = v;
    }
    __syncthreads();
    if (do_proj) {
        int c = t & 63;
        for (int rp = 0; rp < 4; rp++) {
            int rl = rp * 4 + (t >> 6);
            int row = row0 + rl;
            if (row < n) {
                float acc = 0.0f;
#pragma unroll
                for (int k = 0; k < 128; k++) acc = fmaf(xs[rl * 128 + k], Ws[k * 64 + c], acc);
                proj[(size_t)row * 64 + c] = acc + bias[c];
            }
        }
    }
    if (do_copy) {
        for (int i = t; i < 16 * 32; i += 256) {
            int r  = i >> 5;
            int c4 = (i & 31) * 4;
            int row = row0 + r;
            if (row < n)
                *(float4*)(xdst + (size_t)row * 128 + c4) = *(const float4*)&xs[r * 128 + c4];
        }
    }
}

// ---------------- host ----------------
static float* symF(const void* sym) { void* p = nullptr; cudaGetSymbolAddress(&p, sym); return (float*)p; }
static int*   symI(const void* sym) { void* p = nullptr; cudaGetSymbolAddress(&p, sym); return (int*)p; }
static bf16*  symB(const void* sym) { void* p = nullptr; cudaGetSymbolAddress(&p, sym); return (bf16*)p; }

extern "C" void kernel_launch(void* const* d_in, const int* in_sizes, int n_in,
                              void* d_out, int out_size)
{
    const float* x    = (const float*)d_in[0];
    const float* WL   = (const float*)d_in[1];
    const float* bL   = (const float*)d_in[2];
    const float* WG   = (const float*)d_in[3];
    const float* bG   = (const float*)d_in[4];
    const float* linW = (const float*)d_in[5];
    const float* linb = (const float*)d_in[6];
    const float* ln_g = (const float*)d_in[7];
    const float* ln_b = (const float*)d_in[8];
    const float* finW = (const float*)d_in[9];
    const float* finb = (const float*)d_in[10];
    const int*   Gei  = (const int*)d_in[11];
    const int*   Lei  = (const int*)d_in[12];

    int n  = in_sizes[0] / HCH;
    if (n > MAXN) n = MAXN;
    int EG = in_sizes[11] / 2;
    int EL = in_sizes[12] / 2;
    const int *Gsrc = Gei, *Gdst = Gei + EG;
    const int *Lsrc = Lei, *Ldst = Lei + EL;

    float* hL = symF(g_hL); float* hG = symF(g_hG);
    float* aL = symF(g_aL); float* aG = symF(g_aG);
    float* xA = symF(g_xA); float* xB = symF(g_xB);
    float* iL = symF(g_iL); float* iG = symF(g_iG);
    int*   dL = symI(g_dL); int*   dG = symI(g_dG);
    bf16* xhi = symB(g_xhi);   bf16* xlo = symB(g_xlo);
    bf16* aLh = symB(g_aLhi);  bf16* aLl = symB(g_aLlo);
    bf16* aGh = symB(g_aGhi);  bf16* aGl = symB(g_aGlo);
    bf16* whi = symB(g_whi);   bf16* wlo = symB(g_wlo);

    static int attr_done = 0;
    if (!attr_done) {
        cudaFuncSetAttribute(gemm_gcn_dual, cudaFuncAttributeMaxDynamicSharedMemorySize, SM_DUAL);
        cudaFuncSetAttribute(gemm_cat,      cudaFuncAttributeMaxDynamicSharedMemorySize, SM_CAT);
        attr_done = 1;
    }

    const int TB = 256;
    int gbN   = (n + TB - 1) / TB;
    int gbN32 = (n * 32 + TB - 1) / TB;
    int gbT   = (n + 127) / 128;

    // degrees + dinv
    k_degzero<<<gbN, TB>>>(dL, dG, n);
    k_count<<<(EL + TB - 1) / TB, TB>>>(Ldst, EL, dL);
    k_count<<<(EG + TB - 1) / TB, TB>>>(Gdst, EG, dG);
    k_dinv<<<gbN, TB>>>(dL, dG, iL, iG, n);

    // weight + input conversions (bf16 hi/lo)
    k_cvtW<<<(12 * 16384 + TB - 1) / TB, TB>>>(WL, WG, linW, whi, wlo);
    k_cvtX<<<(n * 128 + TB - 1) / TB, TB>>>(x, xhi, xlo, n * 128);

    const float* xin = x;
    float* xout = xA;
    for (int i = 0; i < 3; i++) {
        const bf16* wLh = whi + (size_t)(i * 4 + 0) * 16384;
        const bf16* wLl = wlo + (size_t)(i * 4 + 0) * 16384;
        const bf16* wGh = whi + (size_t)(i * 4 + 1) * 16384;
        const bf16* wGl = wlo + (size_t)(i * 4 + 1) * 16384;
        const bf16* wTh = whi + (size_t)(i * 4 + 2) * 16384;
        const bf16* wTl = wlo + (size_t)(i * 4 + 2) * 16384;
        const bf16* wBh = whi + (size_t)(i * 4 + 3) * 16384;
        const bf16* wBl = wlo + (size_t)(i * 4 + 3) * 16384;
        const float* bLi = bL + i * 128;
        const float* bGi = bG + i * 128;
        const float* lbi = linb + i * 128;

        gemm_gcn_dual<<<gbT, 256, SM_DUAL>>>(xhi, xlo, wLh, wLl, wGh, wGl,
                                             iL, iG, hL, hG, aL, aG, n);
        k_edge<<<(int)(((size_t)EL * 32 + TB - 1) / TB), TB>>>(hL, Lsrc, Ldst, aL, EL);
        k_edge<<<(int)(((size_t)EG * 32 + TB - 1) / TB), TB>>>(hG, Gsrc, Gdst, aG, EG);
        const float* res = (i > 0) ? xin : nullptr;
        k_ln<<<gbN32, TB>>>(aL, iL, bLi, ln_g, ln_b, res, aLh, aLl, n);
        k_ln<<<gbN32, TB>>>(aG, iG, bGi, ln_g, ln_b, res, aGh, aGl, n);
        gemm_cat<<<gbT, 256, SM_CAT>>>(aGh, aGl, aLh, aLl, wTh, wTl, wBh, wBl,
                                       lbi, xout, xhi, xlo, n);
        xin  = xout;
        xout = (xout == xA) ? xB : xA;
    }

    // output layout from out_size: tuple (proj[N,64], x[N,128]) flattened in order
    size_t nP = (size_t)n * 64, nX = (size_t)n * 128;
    float* out = (float*)d_out;
    int do_proj = 1, do_copy = 0;
    float* xdst = nullptr;
    if ((size_t)out_size >= nP + nX)      { do_copy = 1; xdst = out + nP; }
    else if ((size_t)out_size == nX)      { do_proj = 0; do_copy = 1; xdst = out; }
    k_final<<<(n + 15) / 16, TB>>>(xin, finW, finb, out, xdst, n, do_proj, do_copy);
}